// round 14
// baseline (speedup 1.0000x reference)
#include <cuda_runtime.h>

#define HALF_DT 0.05f
#define A1024f 0.0061359231515f   /* 2*pi/1024 */

typedef unsigned long long u64;

// warp-coalesced multiplier table: g_mult4[c*32 + t] packs slots (2c, 2c+1) for thread t
__device__ float4 g_mult4[512];

// packed complex add: one add.rn.f32x2
__device__ __forceinline__ float2 cadd(float2 a, float2 b){
    float2 c;
    asm("add.rn.f32x2 %0, %1, %2;"
        : "=l"(reinterpret_cast<u64&>(c))
        : "l"(reinterpret_cast<const u64&>(a)), "l"(reinterpret_cast<const u64&>(b)));
    return c;
}
// packed complex sub: a - b = fma(b, {-1,-1}, a)
__device__ __forceinline__ float2 csub(float2 a, float2 b){
    float2 c;
    const u64 NEG1 = 0xBF800000BF800000ull;
    asm("fma.rn.f32x2 %0, %1, %2, %3;"
        : "=l"(reinterpret_cast<u64&>(c))
        : "l"(reinterpret_cast<const u64&>(b)), "l"(NEG1), "l"(reinterpret_cast<const u64&>(a)));
    return c;
}
__device__ __forceinline__ float2 cmul(float2 a, float2 b){
    return make_float2(fmaf(a.x, b.x, -a.y*b.y), fmaf(a.x, b.y, a.y*b.x));
}
// sign flip on the ALU pipe (LOP3), not the fma pipe
__device__ __forceinline__ float negf(float x){
    return __uint_as_float(__float_as_uint(x) ^ 0x80000000u);
}

// digit-reversal of the 4-2-4 mixed-radix length-32 FFT (involution)
__device__ __host__ __forceinline__ int sig(int s){ return ((s & 3) << 3) | (s & 4) | (s >> 3); }

// ---------- pre-kernel: spectral Cayley multiplier, coalesced layout ----------
__global__ void build_mult(const float* __restrict__ hw) {
    int q = blockIdx.x * blockDim.x + threadIdx.x;   // 0..1023
    if (q >= 1024) return;
    float w[15];
    #pragma unroll
    for (int k = 0; k < 15; k++) w[k] = hw[k];
    const int offs[11] = {1,2,3,4,5,6,8,10,12,16,20};
    float wm[11];
    wm[0]=w[0]; wm[1]=w[1]+w[5]; wm[2]=w[2]; wm[3]=w[3]+w[6]+w[10]; wm[4]=w[4];
    wm[5]=w[7]; wm[6]=w[8]+w[11]; wm[7]=w[9]; wm[8]=w[12]; wm[9]=w[13]; wm[10]=w[14];
    // q = 64c + 2t + h  ->  float2 index q of g_mult4 holds slot s=2c+h for thread t
    int c = q >> 6, t = (q >> 1) & 31, h = q & 1;
    int s = 2*c + h;
    int f = t + 32 * sig(s);
    float lam = 0.0f;
    #pragma unroll
    for (int k = 0; k < 11; k++)
        lam += 2.0f * wm[k] * (1.0f - cospif((float)(offs[k] * f) * (1.0f/512.0f)));
    float sl  = HALF_DT * lam;
    float den = 1.0f + sl * sl;
    ((float2*)g_mult4)[q] = make_float2((1.0f - sl*sl) / (den * 1024.0f),
                                        (-2.0f * sl)   / (den * 1024.0f));
}

// radix-4 butterfly: DFT4 (INV=false) / IDFT4 (INV=true).
// B/D branch via m = -/+ i*t3 built on ALU pipe, then packed add/sub.
template<bool INV>
__device__ __forceinline__ void bf4(float2& A, float2& B, float2& C, float2& D){
    float2 t0 = cadd(A, C), t1 = csub(A, C);
    float2 t2 = cadd(B, D), t3 = csub(B, D);
    A = cadd(t0, t2); C = csub(t0, t2);
    float2 m;
    if (!INV) { m.x = t3.y;        m.y = negf(t3.x); }   // -i*t3
    else      { m.x = negf(t3.y);  m.y = t3.x;        }  // +i*t3
    B = cadd(t1, m);
    D = csub(t1, m);
}

// in-register length-32 DFT/IDFT (DIF, radix 4-2-4), natural input,
// output slot s holds index sig(s). Twiddles are compile-time table constants.
template<bool INV>
__device__ __forceinline__ void fft32(float2* r){
    // cos/sin(pi*k/16), k = 0..21
    const float CT[22] = { 1.f, 0.98078528f, 0.92387953f, 0.83146961f, 0.70710678f,
                           0.55557023f, 0.38268343f, 0.19509032f, 0.f, -0.19509032f,
                          -0.38268343f, -0.55557023f, -0.70710678f, -0.83146961f,
                          -0.92387953f, -0.98078528f, -1.f, -0.98078528f, -0.92387953f,
                          -0.83146961f, -0.70710678f, -0.55557023f };
    const float ST[22] = { 0.f, 0.19509032f, 0.38268343f, 0.55557023f, 0.70710678f,
                           0.83146961f, 0.92387953f, 0.98078528f, 1.f, 0.98078528f,
                           0.92387953f, 0.83146961f, 0.70710678f, 0.55557023f,
                           0.38268343f, 0.19509032f, 0.f, -0.19509032f, -0.38268343f,
                          -0.55557023f, -0.70710678f, -0.83146961f };
    #pragma unroll
    for (int q = 0; q < 8; q++){
        bf4<INV>(r[q], r[q+8], r[q+16], r[q+24]);
        if (q){
            r[q+8]  = cmul(r[q+8],  make_float2(CT[q],   INV ? ST[q]   : -ST[q]));
            r[q+16] = cmul(r[q+16], make_float2(CT[2*q], INV ? ST[2*q] : -ST[2*q]));
            r[q+24] = cmul(r[q+24], make_float2(CT[3*q], INV ? ST[3*q] : -ST[3*q]));
        }
    }
    const float SQ = 0.70710678118654752f;
    #pragma unroll
    for (int b = 0; b < 4; b++){
        float2* s = r + 8*b;
        #pragma unroll
        for (int q = 0; q < 4; q++){
            float2 d = csub(s[q], s[q+4]);
            s[q] = cadd(s[q], s[q+4]);
            s[q+4] = d;
        }
        if (!INV) {
            s[5] = cmul(s[5], make_float2(SQ, -SQ));
            s[6] = make_float2(s[6].y, negf(s[6].x));       // * (-i)
            s[7] = cmul(s[7], make_float2(-SQ, -SQ));
        } else {
            s[5] = cmul(s[5], make_float2(SQ,  SQ));
            s[6] = make_float2(negf(s[6].y), s[6].x);       // * (+i)
            s[7] = cmul(s[7], make_float2(-SQ,  SQ));
        }
    }
    #pragma unroll
    for (int c = 0; c < 8; c++) bf4<INV>(r[4*c], r[4*c+1], r[4*c+2], r[4*c+3]);
}

// apply r[sig(j)] *= base^j for j=1..31, 4-wide ILP (chain depth 8, not 31)
__device__ __forceinline__ void twiddle_chain(float2* r, float2 base){
    float2 b2 = cmul(base, base);
    float2 b3 = cmul(b2, base);
    float2 b4 = cmul(b2, b2);
    float2 bm[4] = {make_float2(1.0f, 0.0f), base, b2, b3};
    float2 p = make_float2(1.0f, 0.0f);
    #pragma unroll
    for (int k = 0; k < 8; k++){
        #pragma unroll
        for (int m = 0; m < 4; m++){
            int j = 4*k + m;
            if (j) r[sig(j)] = cmul(r[sig(j)], (k == 0) ? bm[m] : cmul(p, bm[m]));
        }
        if (k < 7) p = (k == 0) ? b4 : cmul(p, b4);
    }
}

__global__ __launch_bounds__(32, 22)
void cayley_fft_kernel(const float* __restrict__ psi_r,
                       const float* __restrict__ psi_i,
                       const float* __restrict__ alpha,
                       float2* __restrict__ out) {
    // padded layout: row stride 34 float2 (272B) -> exchange loads are LDS.128,
    // conflict-free in every 16-lane phase on both sides
    __shared__ float2 sx[34 * 32];
    const int t = threadIdx.x;                 // 0..31
    const long long sys = blockIdx.x;
    const float* __restrict__ gr = psi_r + sys * 1024;
    const float* __restrict__ gi = psi_i + sys * 1024;

    // ---- load 32 elems (n = t + 32k, coalesced), intensity ----
    float2 r[32];
    float isum = 0.0f;
    #pragma unroll
    for (int k = 0; k < 32; k++){
        int i = t + 32*k;
        r[k] = make_float2(gr[i], gi[i]);
        isum += r[k].x * r[k].x + r[k].y * r[k].y;
    }
    #pragma unroll
    for (int o = 16; o > 0; o >>= 1) isum += __shfl_xor_sync(0xffffffffu, isum, o);
    const float inv_mean = 1.0f / (isum * (1.0f/1024.0f) + 1e-8f);

    // ---- nonlinear phase rotation ----
    #pragma unroll
    for (int k = 0; k < 32; k++){
        int i = t + 32*k;
        float inten = (r[k].x * r[k].x + r[k].y * r[k].y) * inv_mean;
        float ph = alpha[i] * inten;
        float s, c;
        __sincosf(ph, &s, &c);
        r[k] = make_float2(r[k].x * c - r[k].y * s, r[k].x * s + r[k].y * c);
    }

    // ---- phase 1: FFT32 over k; slot s holds j = sig(s) ----
    fft32<false>(r);

    // inter-phase twiddle W_1024^{t*j}  (base recomputed before inverse: saves 2 live regs)
    {
        float s0, c0;
        __sincosf((float)t * A1024f, &s0, &c0);
        twiddle_chain(r, make_float2(c0, -s0));
    }

    // ---- exchange 1: (j,t) transpose, padded stride, warp-synchronous ----
    {
        float2* __restrict__ st = sx + t;        // store: row sig(s), col t
        #pragma unroll
        for (int s = 0; s < 32; s++) st[34 * sig(s)] = r[s];
    }
    __syncwarp();
    {
        const float4* __restrict__ ld4 = (const float4*)(sx + 34 * t);
        #pragma unroll
        for (int e = 0; e < 16; e++){
            float4 v = ld4[e];
            r[2*e]   = make_float2(v.x, v.y);
            r[2*e+1] = make_float2(v.z, v.w);
        }
    }
    __syncwarp();   // buffer reused by exchange 2

    // ---- phase 2: FFT32 over t; slot s2 holds spectrum at f = j + 32*sig(s2) ----
    fft32<false>(r);

    // ---- spectral multiply: warp-coalesced float4 table loads ----
    {
        const float4* __restrict__ Mp = g_mult4;
        #pragma unroll
        for (int c = 0; c < 16; c++){
            float4 m = Mp[c*32 + t];
            r[2*c]   = cmul(r[2*c],   make_float2(m.x, m.y));
            r[2*c+1] = cmul(r[2*c+1], make_float2(m.z, m.w));
        }
    }

    // ---- reorder slots to natural h order (sig involution: register renames) ----
    #pragma unroll
    for (int d = 0; d < 2; d++)
        #pragma unroll
        for (int b = 0; b < 4; b++)
            #pragma unroll
            for (int e = b + 1; e < 4; e++){
                int i1 = 8*b + 4*d + e, i2 = 8*e + 4*d + b;
                float2 tmp = r[i1]; r[i1] = r[i2]; r[i2] = tmp;
            }

    // ---- phase 3: IFFT32 over h; slot s holds u at position sig(s) ----
    fft32<true>(r);

    // inter-phase twiddle W_1024^{-t*j} (conj base, recomputed)
    {
        float s0, c0;
        __sincosf((float)t * A1024f, &s0, &c0);
        twiddle_chain(r, make_float2(c0, s0));
    }

    // ---- exchange 2: same addressing ----
    {
        float2* __restrict__ st = sx + t;
        #pragma unroll
        for (int s = 0; s < 32; s++) st[34 * sig(s)] = r[s];
    }
    __syncwarp();
    {
        const float4* __restrict__ ld4 = (const float4*)(sx + 34 * t);
        #pragma unroll
        for (int e = 0; e < 16; e++){
            float4 v = ld4[e];
            r[2*e]   = make_float2(v.x, v.y);
            r[2*e+1] = make_float2(v.z, v.w);
        }
    }

    // ---- phase 4: IFFT32 over j; slot s holds x[t + 32*sig(s)] ----
    fft32<true>(r);

    // ---- coalesced store ----
    float2* __restrict__ o = out + sys * 1024 + t;
    #pragma unroll
    for (int s = 0; s < 32; s++) o[32 * sig(s)] = r[s];
}

extern "C" void kernel_launch(void* const* d_in, const int* in_sizes, int n_in,
                              void* d_out, int out_size) {
    const float* psi_r = (const float*)d_in[0];
    const float* psi_i = (const float*)d_in[1];
    const float* alpha = (const float*)d_in[2];
    const float* ham_w = (const float*)d_in[3];
    float2* out = (float2*)d_out;

    const int nsys = in_sizes[0] / 1024;   // B*S = 16384

    build_mult<<<4, 256>>>(ham_w);
    cayley_fft_kernel<<<nsys, 32>>>(psi_r, psi_i, alpha, out);
}

// round 15
// speedup vs baseline: 1.6765x; 1.6765x over previous
#include <cuda_runtime.h>

#define HALF_DT 0.05f
#define A1024f 0.0061359231515f   /* 2*pi/1024 */

typedef unsigned long long u64;

// warp-coalesced multiplier table: g_mult4[c*32 + t] packs slots (2c, 2c+1) for thread t
__device__ float4 g_mult4[512];

// packed complex add: one add.rn.f32x2
__device__ __forceinline__ float2 cadd(float2 a, float2 b){
    float2 c;
    asm("add.rn.f32x2 %0, %1, %2;"
        : "=l"(reinterpret_cast<u64&>(c))
        : "l"(reinterpret_cast<const u64&>(a)), "l"(reinterpret_cast<const u64&>(b)));
    return c;
}
// packed complex sub: a - b = fma(b, {-1,-1}, a)
__device__ __forceinline__ float2 csub(float2 a, float2 b){
    float2 c;
    const u64 NEG1 = 0xBF800000BF800000ull;
    asm("fma.rn.f32x2 %0, %1, %2, %3;"
        : "=l"(reinterpret_cast<u64&>(c))
        : "l"(reinterpret_cast<const u64&>(b)), "l"(NEG1), "l"(reinterpret_cast<const u64&>(a)));
    return c;
}
__device__ __forceinline__ float2 cmul(float2 a, float2 b){
    return make_float2(fmaf(a.x, b.x, -a.y*b.y), fmaf(a.x, b.y, a.y*b.x));
}
// sign flip on the ALU pipe (LOP3), not the fma pipe
__device__ __forceinline__ float negf(float x){
    return __uint_as_float(__float_as_uint(x) ^ 0x80000000u);
}

// digit-reversal of the 4-2-4 mixed-radix length-32 FFT (involution)
__device__ __host__ __forceinline__ int sig(int s){ return ((s & 3) << 3) | (s & 4) | (s >> 3); }

// ---------- pre-kernel: spectral Cayley multiplier, coalesced layout ----------
__global__ void build_mult(const float* __restrict__ hw) {
    int q = blockIdx.x * blockDim.x + threadIdx.x;   // 0..1023
    if (q >= 1024) return;
    float w[15];
    #pragma unroll
    for (int k = 0; k < 15; k++) w[k] = hw[k];
    const int offs[11] = {1,2,3,4,5,6,8,10,12,16,20};
    float wm[11];
    wm[0]=w[0]; wm[1]=w[1]+w[5]; wm[2]=w[2]; wm[3]=w[3]+w[6]+w[10]; wm[4]=w[4];
    wm[5]=w[7]; wm[6]=w[8]+w[11]; wm[7]=w[9]; wm[8]=w[12]; wm[9]=w[13]; wm[10]=w[14];
    // q = 64c + 2t + h  ->  float2 index q of g_mult4 holds slot s=2c+h for thread t
    int c = q >> 6, t = (q >> 1) & 31, h = q & 1;
    int s = 2*c + h;
    int f = t + 32 * sig(s);
    float lam = 0.0f;
    #pragma unroll
    for (int k = 0; k < 11; k++)
        lam += 2.0f * wm[k] * (1.0f - cospif((float)(offs[k] * f) * (1.0f/512.0f)));
    float sl  = HALF_DT * lam;
    float den = 1.0f + sl * sl;
    ((float2*)g_mult4)[q] = make_float2((1.0f - sl*sl) / (den * 1024.0f),
                                        (-2.0f * sl)   / (den * 1024.0f));
}

// radix-4 butterfly: DFT4 (INV=false) / IDFT4 (INV=true).
// B/D branch via m = -/+ i*t3 built on ALU pipe, then packed add/sub.
template<bool INV>
__device__ __forceinline__ void bf4(float2& A, float2& B, float2& C, float2& D){
    float2 t0 = cadd(A, C), t1 = csub(A, C);
    float2 t2 = cadd(B, D), t3 = csub(B, D);
    A = cadd(t0, t2); C = csub(t0, t2);
    float2 m;
    if (!INV) { m.x = t3.y;        m.y = negf(t3.x); }   // -i*t3
    else      { m.x = negf(t3.y);  m.y = t3.x;        }  // +i*t3
    B = cadd(t1, m);
    D = csub(t1, m);
}

// in-register length-32 DFT/IDFT (DIF, radix 4-2-4), natural input,
// output slot s holds index sig(s). Twiddles are compile-time table constants.
template<bool INV>
__device__ __forceinline__ void fft32(float2* r){
    // cos/sin(pi*k/16), k = 0..21
    const float CT[22] = { 1.f, 0.98078528f, 0.92387953f, 0.83146961f, 0.70710678f,
                           0.55557023f, 0.38268343f, 0.19509032f, 0.f, -0.19509032f,
                          -0.38268343f, -0.55557023f, -0.70710678f, -0.83146961f,
                          -0.92387953f, -0.98078528f, -1.f, -0.98078528f, -0.92387953f,
                          -0.83146961f, -0.70710678f, -0.55557023f };
    const float ST[22] = { 0.f, 0.19509032f, 0.38268343f, 0.55557023f, 0.70710678f,
                           0.83146961f, 0.92387953f, 0.98078528f, 1.f, 0.98078528f,
                           0.92387953f, 0.83146961f, 0.70710678f, 0.55557023f,
                           0.38268343f, 0.19509032f, 0.f, -0.19509032f, -0.38268343f,
                          -0.55557023f, -0.70710678f, -0.83146961f };
    #pragma unroll
    for (int q = 0; q < 8; q++){
        bf4<INV>(r[q], r[q+8], r[q+16], r[q+24]);
        if (q){
            r[q+8]  = cmul(r[q+8],  make_float2(CT[q],   INV ? ST[q]   : -ST[q]));
            r[q+16] = cmul(r[q+16], make_float2(CT[2*q], INV ? ST[2*q] : -ST[2*q]));
            r[q+24] = cmul(r[q+24], make_float2(CT[3*q], INV ? ST[3*q] : -ST[3*q]));
        }
    }
    const float SQ = 0.70710678118654752f;
    #pragma unroll
    for (int b = 0; b < 4; b++){
        float2* s = r + 8*b;
        #pragma unroll
        for (int q = 0; q < 4; q++){
            float2 d = csub(s[q], s[q+4]);
            s[q] = cadd(s[q], s[q+4]);
            s[q+4] = d;
        }
        if (!INV) {
            s[5] = cmul(s[5], make_float2(SQ, -SQ));
            s[6] = make_float2(s[6].y, negf(s[6].x));       // * (-i)
            s[7] = cmul(s[7], make_float2(-SQ, -SQ));
        } else {
            s[5] = cmul(s[5], make_float2(SQ,  SQ));
            s[6] = make_float2(negf(s[6].y), s[6].x);       // * (+i)
            s[7] = cmul(s[7], make_float2(-SQ,  SQ));
        }
    }
    #pragma unroll
    for (int c = 0; c < 8; c++) bf4<INV>(r[4*c], r[4*c+1], r[4*c+2], r[4*c+3]);
}

// apply r[sig(j)] *= base^j for j=1..31, 4-wide ILP (chain depth 8, not 31)
__device__ __forceinline__ void twiddle_chain(float2* r, float2 base){
    float2 b2 = cmul(base, base);
    float2 b3 = cmul(b2, base);
    float2 b4 = cmul(b2, b2);
    float2 bm[4] = {make_float2(1.0f, 0.0f), base, b2, b3};
    float2 p = make_float2(1.0f, 0.0f);
    #pragma unroll
    for (int k = 0; k < 8; k++){
        #pragma unroll
        for (int m = 0; m < 4; m++){
            int j = 4*k + m;
            if (j) r[sig(j)] = cmul(r[sig(j)], (k == 0) ? bm[m] : cmul(p, bm[m]));
        }
        if (k < 7) p = (k == 0) ? b4 : cmul(p, b4);
    }
}

__global__ __launch_bounds__(32, 20)
void cayley_fft_kernel(const float* __restrict__ psi_r,
                       const float* __restrict__ psi_i,
                       const float* __restrict__ alpha,
                       float2* __restrict__ out) {
    // padded layout: row stride 34 float2 (272B) -> exchange loads are LDS.128,
    // conflict-free in every 16-lane phase on both sides
    __shared__ float2 sx[34 * 32];
    const int t = threadIdx.x;                 // 0..31
    const long long sys = blockIdx.x;
    const float* __restrict__ gr = psi_r + sys * 1024;
    const float* __restrict__ gi = psi_i + sys * 1024;

    // ---- load 32 elems (n = t + 32k, coalesced), intensity ----
    float2 r[32];
    float isum = 0.0f;
    #pragma unroll
    for (int k = 0; k < 32; k++){
        int i = t + 32*k;
        r[k] = make_float2(gr[i], gi[i]);
        isum += r[k].x * r[k].x + r[k].y * r[k].y;
    }
    #pragma unroll
    for (int o = 16; o > 0; o >>= 1) isum += __shfl_xor_sync(0xffffffffu, isum, o);
    const float inv_mean = 1.0f / (isum * (1.0f/1024.0f) + 1e-8f);

    // ---- nonlinear phase rotation ----
    #pragma unroll
    for (int k = 0; k < 32; k++){
        int i = t + 32*k;
        float inten = (r[k].x * r[k].x + r[k].y * r[k].y) * inv_mean;
        float ph = alpha[i] * inten;
        float s, c;
        __sincosf(ph, &s, &c);
        r[k] = make_float2(r[k].x * c - r[k].y * s, r[k].x * s + r[k].y * c);
    }

    // ---- phase 1: FFT32 over k; slot s holds j = sig(s) ----
    fft32<false>(r);

    // inter-phase twiddle W_1024^{t*j}
    float s0, c0;
    __sincosf((float)t * A1024f, &s0, &c0);
    twiddle_chain(r, make_float2(c0, -s0));

    // ---- exchange 1: (j,t) transpose, padded stride, warp-synchronous ----
    {
        float2* __restrict__ st = sx + t;        // store: row sig(s), col t
        #pragma unroll
        for (int s = 0; s < 32; s++) st[34 * sig(s)] = r[s];
    }
    __syncwarp();
    {
        const float4* __restrict__ ld4 = (const float4*)(sx + 34 * t);
        #pragma unroll
        for (int e = 0; e < 16; e++){
            float4 v = ld4[e];
            r[2*e]   = make_float2(v.x, v.y);
            r[2*e+1] = make_float2(v.z, v.w);
        }
    }
    __syncwarp();   // buffer reused by exchange 2

    // ---- phase 2: FFT32 over t; slot s2 holds spectrum at f = j + 32*sig(s2) ----
    fft32<false>(r);

    // ---- spectral multiply: warp-coalesced float4 table loads ----
    {
        const float4* __restrict__ Mp = g_mult4;
        #pragma unroll
        for (int c = 0; c < 16; c++){
            float4 m = Mp[c*32 + t];
            r[2*c]   = cmul(r[2*c],   make_float2(m.x, m.y));
            r[2*c+1] = cmul(r[2*c+1], make_float2(m.z, m.w));
        }
    }

    // ---- reorder slots to natural h order (sig involution: register renames) ----
    #pragma unroll
    for (int d = 0; d < 2; d++)
        #pragma unroll
        for (int b = 0; b < 4; b++)
            #pragma unroll
            for (int e = b + 1; e < 4; e++){
                int i1 = 8*b + 4*d + e, i2 = 8*e + 4*d + b;
                float2 tmp = r[i1]; r[i1] = r[i2]; r[i2] = tmp;
            }

    // ---- phase 3: IFFT32 over h; slot s holds u at position sig(s) ----
    fft32<true>(r);

    // inter-phase twiddle W_1024^{-t*j} (conj base)
    twiddle_chain(r, make_float2(c0, s0));

    // ---- exchange 2: same addressing ----
    {
        float2* __restrict__ st = sx + t;
        #pragma unroll
        for (int s = 0; s < 32; s++) st[34 * sig(s)] = r[s];
    }
    __syncwarp();
    {
        const float4* __restrict__ ld4 = (const float4*)(sx + 34 * t);
        #pragma unroll
        for (int e = 0; e < 16; e++){
            float4 v = ld4[e];
            r[2*e]   = make_float2(v.x, v.y);
            r[2*e+1] = make_float2(v.z, v.w);
        }
    }

    // ---- phase 4: IFFT32 over j; slot s holds x[t + 32*sig(s)] ----
    fft32<true>(r);

    // ---- coalesced store ----
    float2* __restrict__ o = out + sys * 1024 + t;
    #pragma unroll
    for (int s = 0; s < 32; s++) o[32 * sig(s)] = r[s];
}

extern "C" void kernel_launch(void* const* d_in, const int* in_sizes, int n_in,
                              void* d_out, int out_size) {
    const float* psi_r = (const float*)d_in[0];
    const float* psi_i = (const float*)d_in[1];
    const float* alpha = (const float*)d_in[2];
    const float* ham_w = (const float*)d_in[3];
    float2* out = (float2*)d_out;

    const int nsys = in_sizes[0] / 1024;   // B*S = 16384

    build_mult<<<4, 256>>>(ham_w);
    cayley_fft_kernel<<<nsys, 32>>>(psi_r, psi_i, alpha, out);
}